// round 9
// baseline (speedup 1.0000x reference)
#include <cuda_runtime.h>

#define TT 512
#define BB 64
#define II 1024
#define HH 1024
#define UPITCH 1026   // padded smem pitch (floats)

// h3 exchange buffer, [parity][h-index][b]; b contiguous for coalesced staging
__device__ float g_h3[2][HH][BB];
// dataflow flags: g_ready[bgid*32 + cgid] = number of h3 states published
__device__ unsigned int g_ready4[4 * 32];
// teardown ack counters (row-scoped, padded)
__device__ unsigned int g_ack1[4 * 32];
__device__ unsigned int g_ack2[4 * 32];

__device__ __forceinline__ unsigned long long pk2(float lo, float hi) {
    unsigned long long r;
    asm("mov.b64 %0, {%1, %2};" : "=l"(r) : "f"(lo), "f"(hi));
    return r;
}
__device__ __forceinline__ unsigned long long ffma2(unsigned long long a,
                                                    unsigned long long b,
                                                    unsigned long long c) {
    unsigned long long d;
    asm("fma.rn.f32x2 %0, %1, %2, %3;" : "=l"(d) : "l"(a), "l"(b), "l"(c));
    return d;
}
__device__ __forceinline__ float psum(unsigned long long p) {
    float lo = __uint_as_float((unsigned int)(p & 0xFFFFFFFFull));
    float hi = __uint_as_float((unsigned int)(p >> 32));
    return lo + hi;
}
__device__ __forceinline__ void st_pair4(float* p, float4 v) {
    *(unsigned long long*)(p)     = pk2(v.x, v.y);
    *(unsigned long long*)(p + 2) = pk2(v.z, v.w);
}

// ---------------------------------------------------------------------------
// xw = x @ W^T + bW  (M=32768, N=1024, K=1024) -> d_out.  (R5 best version.)
// ---------------------------------------------------------------------------
__global__ __launch_bounds__(256, 1)
void gemm_xw_kernel(const float* __restrict__ X, const float* __restrict__ W,
                    const float* __restrict__ bW, float* __restrict__ C) {
    __shared__ float xs[128][18];
    __shared__ float ws[128][18];

    const int tid = threadIdx.x;
    const int m0 = blockIdx.y * 128;
    const int n0 = blockIdx.x * 128;
    const int tm = tid & 15;
    const int tn = tid >> 4;
    const int lr = tid >> 2;
    const int lc = (tid & 3) << 2;

    const float* xg = X + (size_t)(m0 + lr) * II + lc;
    const float* wg = W + (size_t)(n0 + lr) * II + lc;

    unsigned long long acc[8][8];
#pragma unroll
    for (int i = 0; i < 8; i++)
#pragma unroll
        for (int j = 0; j < 8; j++) acc[i][j] = 0ull;

    float4 xa = *(const float4*)(xg);
    float4 xb = *(const float4*)(xg + 64 * II);
    float4 wa = *(const float4*)(wg);
    float4 wb = *(const float4*)(wg + 64 * II);

    for (int k0 = 0; k0 < II; k0 += 16) {
        __syncthreads();
        st_pair4(&xs[lr][lc], xa);
        st_pair4(&xs[lr + 64][lc], xb);
        st_pair4(&ws[lr][lc], wa);
        st_pair4(&ws[lr + 64][lc], wb);
        __syncthreads();
        if (k0 + 16 < II) {
            xa = *(const float4*)(xg + k0 + 16);
            xb = *(const float4*)(xg + 64 * II + k0 + 16);
            wa = *(const float4*)(wg + k0 + 16);
            wb = *(const float4*)(wg + 64 * II + k0 + 16);
        }
#pragma unroll
        for (int kp = 0; kp < 8; kp++) {
            unsigned long long af[8], bf[8];
#pragma unroll
            for (int i = 0; i < 8; i++)
                af[i] = *(const unsigned long long*)&xs[tm + 16 * i][kp * 2];
#pragma unroll
            for (int j = 0; j < 8; j++)
                bf[j] = *(const unsigned long long*)&ws[tn + 16 * j][kp * 2];
#pragma unroll
            for (int i = 0; i < 8; i++)
#pragma unroll
                for (int j = 0; j < 8; j++)
                    acc[i][j] = ffma2(af[i], bf[j], acc[i][j]);
        }
    }

#pragma unroll
    for (int i = 0; i < 8; i++) {
        const int m = m0 + tm + 16 * i;
#pragma unroll
        for (int j = 0; j < 8; j++) {
            const int n = n0 + tn + 16 * j;
            C[(size_t)m * HH + n] = psum(acc[i][j]) + bW[n];
        }
    }
}

// ---------------------------------------------------------------------------
// Persistent recurrence, dataflow-flag version.
// 128 CTAs = 4(b) x 32(c) tiles of 16b x 32c. Warp w owns k strip
// [128w, 128w+128) and waits only on its 4 producers' flags, then stages
// its strip and computes autonomously. 2 syncthreads per step.
// ---------------------------------------------------------------------------
__global__ __launch_bounds__(256, 1)
void rnn_steps_kernel(const float* __restrict__ U, const float* __restrict__ bU,
                      float* __restrict__ out) {
    extern __shared__ float fsmem[];
    float* Usm = fsmem;                  // 32 * UPITCH
    float* Hsm = fsmem + 32 * UPITCH;    // 16 * UPITCH
    float* red = fsmem + 48 * UPITCH;    // 8 * 512

    const int tid = threadIdx.x;
    const int cgid = blockIdx.x & 31;
    const int bgid = blockIdx.x >> 5;
    const int c0 = cgid * 32;
    const int b0 = bgid * 16;
    const int bslot = bgid * 32;
    const int myflag = bgid * 32 + cgid;

    for (int idx = tid; idx < 32 * 1024; idx += 256) {
        const int r = idx >> 10, k = idx & 1023;
        Usm[r * UPITCH + k] = U[(size_t)(c0 + r) * HH + k];
    }

    const int o0 = 2 * tid;
    const int blo = o0 >> 5;
    const int clo = o0 & 31;
    const int b = b0 + blo;
    const int c = c0 + clo;
    const float bu0 = bU[c];
    const float bu1 = bU[c + 1];

    const int w = tid >> 5;
    const int lane = tid & 31;
    const int bg = lane & 3;
    const int cg = lane >> 2;
    const int wbase = w * 128;           // this warp's k strip

    // staging mapping within the strip: lane -> (sg, kq)
    const int sg = lane & 3;             // b quad
    const int kq = lane >> 2;            // k offset 0..7
    // this warp's 4 producer flags (lane&3 selects one)
    const volatile unsigned int* fp =
        (const volatile unsigned int*)&g_ready4[bgid * 32 + 4 * w + (lane & 3)];

    __syncthreads();

    // t = 0 : h3(0) = tanh(xw_0)
    {
        const size_t idx = ((size_t)b * TT) * HH + c;
        const float2 xw = *(const float2*)&out[idx];
        const float h0 = tanhf(xw.x);
        const float h1 = tanhf(xw.y);
        out[idx] = h0;
        out[idx + 1] = h1;
        g_h3[0][c][b] = h0;
        g_h3[0][c + 1][b] = h1;
    }
    __syncthreads();
    if (tid == 0) {
        __threadfence();
        *(volatile unsigned int*)&g_ready4[myflag] = 1u;
    }

    for (int t = 0; t < TT - 1; t++) {
        const int par = t & 1;
        const size_t nidx = ((size_t)b * TT + (t + 1)) * HH + c;
        const float2 xwn = *(const float2*)&out[nidx];
        const float* hb = &g_h3[par][0][0];

        // ---- wait for this warp's 4 producers (h3(t) strips ready) ----
        {
            const unsigned int tgt = (unsigned int)(t + 1);
            while (!__all_sync(0xffffffffu, *fp >= tgt)) { }
        }
        __threadfence();

        // ---- stage this warp's strip: 128 k x 16 b (2 batches of 8) ----
#pragma unroll
        for (int half = 0; half < 2; half++) {
            float4 v[8];
#pragma unroll
            for (int it = 0; it < 8; it++) {
                const int k = wbase + kq + 8 * (half * 8 + it);
                v[it] = __ldcg((const float4*)(hb + (size_t)k * BB + b0 + 4 * sg));
            }
#pragma unroll
            for (int it = 0; it < 8; it++) {
                const int k = wbase + kq + 8 * (half * 8 + it);
                float* dst = Hsm + k;
                dst[(4 * sg + 0) * UPITCH] = v[it].x;
                dst[(4 * sg + 1) * UPITCH] = v[it].y;
                dst[(4 * sg + 2) * UPITCH] = v[it].z;
                dst[(4 * sg + 3) * UPITCH] = v[it].w;
            }
        }
        __syncwarp();

        // ---- compute: strip GEMM, pure LDS.64 + FFMA2 ----
        unsigned long long acc[4][4];
#pragma unroll
        for (int i = 0; i < 4; i++)
#pragma unroll
            for (int q = 0; q < 4; q++) acc[i][q] = 0ull;

#pragma unroll 8
        for (int kp = 0; kp < 64; kp++) {
            const int k0 = wbase + 2 * kp;
            unsigned long long a[4], u[4];
#pragma unroll
            for (int i = 0; i < 4; i++)
                a[i] = *(const unsigned long long*)&Hsm[(i * 4 + bg) * UPITCH + k0];
#pragma unroll
            for (int q = 0; q < 4; q++)
                u[q] = *(const unsigned long long*)&Usm[(q * 8 + cg) * UPITCH + k0];
#pragma unroll
            for (int i = 0; i < 4; i++)
#pragma unroll
                for (int q = 0; q < 4; q++)
                    acc[i][q] = ffma2(a[i], u[q], acc[i][q]);
        }

        // warp partials -> red
#pragma unroll
        for (int i = 0; i < 4; i++) {
            const int ob = (i * 4 + bg) * 32;
#pragma unroll
            for (int q = 0; q < 4; q++)
                red[w * 512 + ob + q * 8 + cg] = psum(acc[i][q]);
        }
        __syncthreads();   // red writes visible

        float s0 = bu0, s1 = bu1;
#pragma unroll
        for (int ww = 0; ww < 8; ww++) {
            const float2 p = *(const float2*)&red[ww * 512 + o0];
            s0 += p.x;
            s1 += p.y;
        }

        const float h0 = tanhf(xwn.x + s0);
        const float h1 = tanhf(xwn.y + s1);
        out[nidx] = h0;
        out[nidx + 1] = h1;
        const int par1 = par ^ 1;
        g_h3[par1][c][b] = h0;
        g_h3[par1][c + 1][b] = h1;

        if (t == TT - 2) {
            const size_t o2 = (size_t)BB * TT * HH + (size_t)b * HH + c;
            out[o2] = h0;
            out[o2 + 1] = h1;
            break;
        }

        __syncthreads();   // all h3 writes done (also orders next red WAR)
        if (tid == 0) {
            __threadfence();
            *(volatile unsigned int*)&g_ready4[myflag] = (unsigned int)(t + 2);
        }
    }

    // ---- replay-safe teardown: reset own flag after all row peers are done ----
    __syncthreads();
    if (tid == 0) {
        atomicAdd(&g_ack1[bslot], 1);
        while (*(volatile unsigned int*)&g_ack1[bslot] < 32u) { }
        *(volatile unsigned int*)&g_ready4[myflag] = 0u;   // nobody polls anymore
        __threadfence();
        const unsigned int y = atomicAdd(&g_ack2[bslot], 1);
        if (y == 31u) {        // last: all did ack1-pass + flag reset
            g_ack1[bslot] = 0;
            g_ack2[bslot] = 0;
            __threadfence();
        }
    }
}

extern "C" void kernel_launch(void* const* d_in, const int* in_sizes, int n_in,
                              void* d_out, int out_size) {
    const float* x  = (const float*)d_in[0];
    const float* W  = (const float*)d_in[1];
    const float* bW = (const float*)d_in[2];
    const float* U  = (const float*)d_in[3];
    const float* bU = (const float*)d_in[4];
    float* out = (float*)d_out;

    const int rnn_smem = (48 * UPITCH + 8 * 512) * sizeof(float);
    cudaFuncSetAttribute(rnn_steps_kernel,
                         cudaFuncAttributeMaxDynamicSharedMemorySize, rnn_smem);

    dim3 ggrid(HH / 128, (BB * TT) / 128);  // (8, 256)
    gemm_xw_kernel<<<ggrid, 256>>>(x, W, bW, out);

    rnn_steps_kernel<<<128, 256, rnn_smem>>>(U, bU, out);
}

// round 10
// speedup vs baseline: 1.9622x; 1.9622x over previous
#include <cuda_runtime.h>

#define TT 512
#define BB 64
#define II 1024
#define HH 1024
#define UPITCH 1026   // padded smem pitch (floats)

// h3 exchange buffer, [parity][h-index][b]; b contiguous for coalesced staging
__device__ float g_h3[2][HH][BB];
// per-CTA monotone step flags, one 128B line per row
__device__ __align__(128) unsigned int g_stepflag[4][32];
// teardown ack counters (row-scoped, padded)
__device__ unsigned int g_ack1[4 * 32];
__device__ unsigned int g_ack2[4 * 32];

__device__ __forceinline__ unsigned long long pk2(float lo, float hi) {
    unsigned long long r;
    asm("mov.b64 %0, {%1, %2};" : "=l"(r) : "f"(lo), "f"(hi));
    return r;
}
__device__ __forceinline__ unsigned long long ffma2(unsigned long long a,
                                                    unsigned long long b,
                                                    unsigned long long c) {
    unsigned long long d;
    asm("fma.rn.f32x2 %0, %1, %2, %3;" : "=l"(d) : "l"(a), "l"(b), "l"(c));
    return d;
}
__device__ __forceinline__ float psum(unsigned long long p) {
    float lo = __uint_as_float((unsigned int)(p & 0xFFFFFFFFull));
    float hi = __uint_as_float((unsigned int)(p >> 32));
    return lo + hi;
}
__device__ __forceinline__ void st_pair4(float* p, float4 v) {
    *(unsigned long long*)(p)     = pk2(v.x, v.y);
    *(unsigned long long*)(p + 2) = pk2(v.z, v.w);
}

// ---------------------------------------------------------------------------
// xw = x @ W^T + bW  (M=32768, N=1024, K=1024) -> d_out.  (R5 best version.)
// ---------------------------------------------------------------------------
__global__ __launch_bounds__(256, 1)
void gemm_xw_kernel(const float* __restrict__ X, const float* __restrict__ W,
                    const float* __restrict__ bW, float* __restrict__ C) {
    __shared__ float xs[128][18];
    __shared__ float ws[128][18];

    const int tid = threadIdx.x;
    const int m0 = blockIdx.y * 128;
    const int n0 = blockIdx.x * 128;
    const int tm = tid & 15;
    const int tn = tid >> 4;
    const int lr = tid >> 2;
    const int lc = (tid & 3) << 2;

    const float* xg = X + (size_t)(m0 + lr) * II + lc;
    const float* wg = W + (size_t)(n0 + lr) * II + lc;

    unsigned long long acc[8][8];
#pragma unroll
    for (int i = 0; i < 8; i++)
#pragma unroll
        for (int j = 0; j < 8; j++) acc[i][j] = 0ull;

    float4 xa = *(const float4*)(xg);
    float4 xb = *(const float4*)(xg + 64 * II);
    float4 wa = *(const float4*)(wg);
    float4 wb = *(const float4*)(wg + 64 * II);

    for (int k0 = 0; k0 < II; k0 += 16) {
        __syncthreads();
        st_pair4(&xs[lr][lc], xa);
        st_pair4(&xs[lr + 64][lc], xb);
        st_pair4(&ws[lr][lc], wa);
        st_pair4(&ws[lr + 64][lc], wb);
        __syncthreads();
        if (k0 + 16 < II) {
            xa = *(const float4*)(xg + k0 + 16);
            xb = *(const float4*)(xg + 64 * II + k0 + 16);
            wa = *(const float4*)(wg + k0 + 16);
            wb = *(const float4*)(wg + 64 * II + k0 + 16);
        }
#pragma unroll
        for (int kp = 0; kp < 8; kp++) {
            unsigned long long af[8], bf[8];
#pragma unroll
            for (int i = 0; i < 8; i++)
                af[i] = *(const unsigned long long*)&xs[tm + 16 * i][kp * 2];
#pragma unroll
            for (int j = 0; j < 8; j++)
                bf[j] = *(const unsigned long long*)&ws[tn + 16 * j][kp * 2];
#pragma unroll
            for (int i = 0; i < 8; i++)
#pragma unroll
                for (int j = 0; j < 8; j++)
                    acc[i][j] = ffma2(af[i], bf[j], acc[i][j]);
        }
    }

#pragma unroll
    for (int i = 0; i < 8; i++) {
        const int m = m0 + tm + 16 * i;
#pragma unroll
        for (int j = 0; j < 8; j++) {
            const int n = n0 + tn + 16 * j;
            C[(size_t)m * HH + n] = psum(acc[i][j]) + bW[n];
        }
    }
}

// ---------------------------------------------------------------------------
// Persistent recurrence (R5 structure; barrier = flag array + warp0 poll).
// 128 CTAs = 4(b) x 32(c) tiles of 16b x 32c. Warp w owns k-strips {w, w+8};
// staging of half1 overlaps pass1 compute.
// ---------------------------------------------------------------------------
__global__ __launch_bounds__(256, 1)
void rnn_steps_kernel(const float* __restrict__ U, const float* __restrict__ bU,
                      float* __restrict__ out) {
    extern __shared__ float fsmem[];
    float* Usm = fsmem;                  // 32 * UPITCH
    float* Hsm = fsmem + 32 * UPITCH;    // 16 * UPITCH
    float* red = fsmem + 48 * UPITCH;    // 8 * 512

    const int tid = threadIdx.x;
    const int cgid = blockIdx.x & 31;
    const int bgid = blockIdx.x >> 5;
    const int c0 = cgid * 32;
    const int b0 = bgid * 16;
    const int bslot = bgid * 32;

    for (int idx = tid; idx < 32 * 1024; idx += 256) {
        const int r = idx >> 10, k = idx & 1023;
        Usm[r * UPITCH + k] = U[(size_t)(c0 + r) * HH + k];
    }

    const int o0 = 2 * tid;
    const int blo = o0 >> 5;
    const int clo = o0 & 31;
    const int b = b0 + blo;
    const int c = c0 + clo;
    const float bu0 = bU[c];
    const float bu1 = bU[c + 1];

    const int w = tid >> 5;
    const int lane = tid & 31;
    const int bg = lane & 3;
    const int cg = lane >> 2;
    const int kb1 = w * 64;
    const int kb2 = 512 + w * 64;

    const int sg = tid & 3;
    const int sk = tid >> 2;

    // warp-0 poll pointer: lane L watches row flag L
    volatile unsigned int* fl = &g_stepflag[bgid][lane];
    volatile unsigned int* myflag = &g_stepflag[bgid][cgid];

    __syncthreads();

    // t = 0 : h3(0) = tanh(xw_0)
    {
        const size_t idx = ((size_t)b * TT) * HH + c;
        const float2 xw = *(const float2*)&out[idx];
        const float h0 = tanhf(xw.x);
        const float h1 = tanhf(xw.y);
        out[idx] = h0;
        out[idx + 1] = h1;
        g_h3[0][c][b] = h0;
        g_h3[0][c + 1][b] = h1;
    }
    __syncthreads();
    if (tid == 0) {
        __threadfence();
        *myflag = 1u;
    }

    for (int t = 0; t < TT - 1; t++) {
        const int par = t & 1;

        // ---- wait: all 32 row peers published h3(t) (flag >= t+1) ----
        if (w == 0) {
            const unsigned int tgt = (unsigned int)(t + 1);
            while (!__all_sync(0xffffffffu, *fl >= tgt)) { }
        }
        __syncthreads();

        const size_t nidx = ((size_t)b * TT + (t + 1)) * HH + c;
        const float2 xwn = *(const float2*)&out[nidx];
        const float* hb = &g_h3[par][0][0];

        // ---- stage half0 (k < 512) ----
        {
            float4 v[8];
#pragma unroll
            for (int it = 0; it < 8; it++) {
                const int k = sk + 64 * it;
                v[it] = __ldcg((const float4*)(hb + (size_t)k * BB + b0 + 4 * sg));
            }
#pragma unroll
            for (int it = 0; it < 8; it++) {
                const int k = sk + 64 * it;
                float* dst = Hsm + k;
                dst[(4 * sg + 0) * UPITCH] = v[it].x;
                dst[(4 * sg + 1) * UPITCH] = v[it].y;
                dst[(4 * sg + 2) * UPITCH] = v[it].z;
                dst[(4 * sg + 3) * UPITCH] = v[it].w;
            }
        }
        __syncthreads();

        // ---- issue half1 LDGs, hidden under pass1 ----
        float4 v1[8];
#pragma unroll
        for (int it = 0; it < 8; it++) {
            const int k = 512 + sk + 64 * it;
            v1[it] = __ldcg((const float4*)(hb + (size_t)k * BB + b0 + 4 * sg));
        }

        unsigned long long acc[4][4];
#pragma unroll
        for (int i = 0; i < 4; i++)
#pragma unroll
            for (int q = 0; q < 4; q++) acc[i][q] = 0ull;

#pragma unroll 8
        for (int kp = 0; kp < 32; kp++) {
            const int k0 = kb1 + 2 * kp;
            unsigned long long a[4], u[4];
#pragma unroll
            for (int i = 0; i < 4; i++)
                a[i] = *(const unsigned long long*)&Hsm[(i * 4 + bg) * UPITCH + k0];
#pragma unroll
            for (int q = 0; q < 4; q++)
                u[q] = *(const unsigned long long*)&Usm[(q * 8 + cg) * UPITCH + k0];
#pragma unroll
            for (int i = 0; i < 4; i++)
#pragma unroll
                for (int q = 0; q < 4; q++)
                    acc[i][q] = ffma2(a[i], u[q], acc[i][q]);
        }

#pragma unroll
        for (int it = 0; it < 8; it++) {
            const int k = 512 + sk + 64 * it;
            float* dst = Hsm + k;
            dst[(4 * sg + 0) * UPITCH] = v1[it].x;
            dst[(4 * sg + 1) * UPITCH] = v1[it].y;
            dst[(4 * sg + 2) * UPITCH] = v1[it].z;
            dst[(4 * sg + 3) * UPITCH] = v1[it].w;
        }
        __syncthreads();

#pragma unroll 8
        for (int kp = 0; kp < 32; kp++) {
            const int k0 = kb2 + 2 * kp;
            unsigned long long a[4], u[4];
#pragma unroll
            for (int i = 0; i < 4; i++)
                a[i] = *(const unsigned long long*)&Hsm[(i * 4 + bg) * UPITCH + k0];
#pragma unroll
            for (int q = 0; q < 4; q++)
                u[q] = *(const unsigned long long*)&Usm[(q * 8 + cg) * UPITCH + k0];
#pragma unroll
            for (int i = 0; i < 4; i++)
#pragma unroll
                for (int q = 0; q < 4; q++)
                    acc[i][q] = ffma2(a[i], u[q], acc[i][q]);
        }

#pragma unroll
        for (int i = 0; i < 4; i++) {
            const int ob = (i * 4 + bg) * 32;
#pragma unroll
            for (int q = 0; q < 4; q++)
                red[w * 512 + ob + q * 8 + cg] = psum(acc[i][q]);
        }
        __syncthreads();

        float s0 = bu0, s1 = bu1;
#pragma unroll
        for (int ww = 0; ww < 8; ww++) {
            const float2 p = *(const float2*)&red[ww * 512 + o0];
            s0 += p.x;
            s1 += p.y;
        }

        const float h0 = tanhf(xwn.x + s0);
        const float h1 = tanhf(xwn.y + s1);
        out[nidx] = h0;
        out[nidx + 1] = h1;
        const int par1 = par ^ 1;
        g_h3[par1][c][b] = h0;
        g_h3[par1][c + 1][b] = h1;

        if (t == TT - 2) {
            const size_t o2 = (size_t)BB * TT * HH + (size_t)b * HH + c;
            out[o2] = h0;
            out[o2 + 1] = h1;
            break;
        }

        __syncthreads();   // all h3(t+1) writes done; also orders red/Hsm WAR
        if (tid == 0) {
            __threadfence();
            *myflag = (unsigned int)(t + 2);
        }
    }

    // ---- replay-safe teardown (R9-proven): reset own flag after row quiesce ----
    __syncthreads();
    if (tid == 0) {
        atomicAdd(&g_ack1[bslot], 1);
        while (*(volatile unsigned int*)&g_ack1[bslot] < 32u) { }
        *myflag = 0u;                       // nobody polls anymore
        __threadfence();
        const unsigned int y = atomicAdd(&g_ack2[bslot], 1);
        if (y == 31u) {
            g_ack1[bslot] = 0;
            g_ack2[bslot] = 0;
            __threadfence();
        }
    }
}

extern "C" void kernel_launch(void* const* d_in, const int* in_sizes, int n_in,
                              void* d_out, int out_size) {
    const float* x  = (const float*)d_in[0];
    const float* W  = (const float*)d_in[1];
    const float* bW = (const float*)d_in[2];
    const float* U  = (const float*)d_in[3];
    const float* bU = (const float*)d_in[4];
    float* out = (float*)d_out;

    const int rnn_smem = (48 * UPITCH + 8 * 512) * sizeof(float);
    cudaFuncSetAttribute(rnn_steps_kernel,
                         cudaFuncAttributeMaxDynamicSharedMemorySize, rnn_smem);

    dim3 ggrid(HH / 128, (BB * TT) / 128);  // (8, 256)
    gemm_xw_kernel<<<ggrid, 256>>>(x, W, bW, out);

    rnn_steps_kernel<<<128, 256, rnn_smem>>>(U, bU, out);
}

// round 15
// speedup vs baseline: 2.3511x; 1.1982x over previous
#include <cuda_runtime.h>

#define TT 512
#define BB 64
#define II 1024
#define HH 1024
#define UPITCH 1026   // padded smem pitch (floats)

// h3 exchange buffer, [parity][h-index][b]; b contiguous for coalesced staging
__device__ float g_h3[2][HH][BB];
// row-scoped barrier state: 4 rows, padded 128B apart (reset by gemm block 0,0)
__device__ unsigned int g_cnt4[4 * 32];
__device__ volatile unsigned int g_flag4[4 * 32];

__device__ __forceinline__ unsigned long long pk2(float lo, float hi) {
    unsigned long long r;
    asm("mov.b64 %0, {%1, %2};" : "=l"(r) : "f"(lo), "f"(hi));
    return r;
}
__device__ __forceinline__ unsigned long long ffma2(unsigned long long a,
                                                    unsigned long long b,
                                                    unsigned long long c) {
    unsigned long long d;
    asm("fma.rn.f32x2 %0, %1, %2, %3;" : "=l"(d) : "l"(a), "l"(b), "l"(c));
    return d;
}
__device__ __forceinline__ float psum(unsigned long long p) {
    float lo = __uint_as_float((unsigned int)(p & 0xFFFFFFFFull));
    float hi = __uint_as_float((unsigned int)(p >> 32));
    return lo + hi;
}
__device__ __forceinline__ void st_pair4(float* p, float4 v) {
    *(unsigned long long*)(p)     = pk2(v.x, v.y);
    *(unsigned long long*)(p + 2) = pk2(v.z, v.w);
}

// ---------------------------------------------------------------------------
// xw = x @ W^T + bW  (M=32768, N=1024, K=1024) -> d_out.  (R5 best version.)
// Block (0,0) resets the row-barrier state for the following kernel.
// ---------------------------------------------------------------------------
__global__ __launch_bounds__(256, 1)
void gemm_xw_kernel(const float* __restrict__ X, const float* __restrict__ W,
                    const float* __restrict__ bW, float* __restrict__ C) {
    if (blockIdx.x == 0 && blockIdx.y == 0 && threadIdx.x < 4) {
        g_cnt4[threadIdx.x * 32] = 0;
        g_flag4[threadIdx.x * 32] = 0;
    }

    __shared__ float xs[128][18];
    __shared__ float ws[128][18];

    const int tid = threadIdx.x;
    const int m0 = blockIdx.y * 128;
    const int n0 = blockIdx.x * 128;
    const int tm = tid & 15;
    const int tn = tid >> 4;
    const int lr = tid >> 2;
    const int lc = (tid & 3) << 2;

    const float* xg = X + (size_t)(m0 + lr) * II + lc;
    const float* wg = W + (size_t)(n0 + lr) * II + lc;

    unsigned long long acc[8][8];
#pragma unroll
    for (int i = 0; i < 8; i++)
#pragma unroll
        for (int j = 0; j < 8; j++) acc[i][j] = 0ull;

    float4 xa = *(const float4*)(xg);
    float4 xb = *(const float4*)(xg + 64 * II);
    float4 wa = *(const float4*)(wg);
    float4 wb = *(const float4*)(wg + 64 * II);

    for (int k0 = 0; k0 < II; k0 += 16) {
        __syncthreads();
        st_pair4(&xs[lr][lc], xa);
        st_pair4(&xs[lr + 64][lc], xb);
        st_pair4(&ws[lr][lc], wa);
        st_pair4(&ws[lr + 64][lc], wb);
        __syncthreads();
        if (k0 + 16 < II) {
            xa = *(const float4*)(xg + k0 + 16);
            xb = *(const float4*)(xg + 64 * II + k0 + 16);
            wa = *(const float4*)(wg + k0 + 16);
            wb = *(const float4*)(wg + 64 * II + k0 + 16);
        }
#pragma unroll
        for (int kp = 0; kp < 8; kp++) {
            unsigned long long af[8], bf[8];
#pragma unroll
            for (int i = 0; i < 8; i++)
                af[i] = *(const unsigned long long*)&xs[tm + 16 * i][kp * 2];
#pragma unroll
            for (int j = 0; j < 8; j++)
                bf[j] = *(const unsigned long long*)&ws[tn + 16 * j][kp * 2];
#pragma unroll
            for (int i = 0; i < 8; i++)
#pragma unroll
                for (int j = 0; j < 8; j++)
                    acc[i][j] = ffma2(af[i], bf[j], acc[i][j]);
        }
    }

#pragma unroll
    for (int i = 0; i < 8; i++) {
        const int m = m0 + tm + 16 * i;
#pragma unroll
        for (int j = 0; j < 8; j++) {
            const int n = n0 + tn + 16 * j;
            C[(size_t)m * HH + n] = psum(acc[i][j]) + bW[n];
        }
    }
}

// ---------------------------------------------------------------------------
// Persistent recurrence, 512 threads (16 warps) per CTA for latency hiding.
// 128 CTAs = 4(b) x 32(c) tiles of 16b x 32c. Warp w owns k-strips
// {w*32, 512+w*32}; staging of half1 overlaps pass1 compute.
// Barrier: R5 row-scoped atomic (1 polling thread per CTA — proven optimum).
// ---------------------------------------------------------------------------
__global__ __launch_bounds__(512, 1)
void rnn_steps_kernel(const float* __restrict__ U, const float* __restrict__ bU,
                      float* __restrict__ out) {
    extern __shared__ float fsmem[];
    float* Usm = fsmem;                  // 32 * UPITCH  (131.3 KB)
    float* Hsm = fsmem + 32 * UPITCH;    // 16 * UPITCH  (65.7 KB)
    float* red = fsmem + 48 * UPITCH;    // 16 * 512     (32.8 KB)

    const int tid = threadIdx.x;
    const int cgid = blockIdx.x & 31;
    const int bgid = blockIdx.x >> 5;
    const int c0 = cgid * 32;
    const int b0 = bgid * 16;
    const int bslot = bgid * 32;

    for (int idx = tid; idx < 32 * 1024; idx += 512) {
        const int r = idx >> 10, k = idx & 1023;
        Usm[r * UPITCH + k] = U[(size_t)(c0 + r) * HH + k];
    }

    const int w = tid >> 5;              // 0..15
    const int lane = tid & 31;

    // this thread's single output within the tile
    const int b = b0 + w;
    const int c = c0 + lane;
    const float bu = bU[c];

    // compute lane mapping (per warp: full 16b x 32c tile, 32-k strips)
    const int bg = lane & 3;
    const int cg = lane >> 2;
    const int kb1 = w * 32;              // pass1 strip (k < 512)
    const int kb2 = 512 + w * 32;        // pass2 strip (k >= 512)

    // staging mapping: 512 threads cover 512 k x 4 b-quads per batch
    const int sg = tid & 3;
    const int sk = tid >> 2;             // 0..127, k = sk + 128*it

    __syncthreads();

    // t = 0 : h3(0) = tanh(xw_0)
    {
        const size_t idx = ((size_t)b * TT) * HH + c;
        const float h0 = tanhf(out[idx]);
        out[idx] = h0;
        g_h3[0][c][b] = h0;
    }
    __threadfence();
    __syncthreads();
    if (tid == 0) {
        if (atomicAdd(&g_cnt4[bslot], 1) == 31) {
            g_cnt4[bslot] = 0;
            __threadfence();
            g_flag4[bslot] = 1;
        } else {
            while (g_flag4[bslot] < 1u) { }
        }
    }
    __syncthreads();

    for (int t = 0; t < TT - 1; t++) {
        const int par = t & 1;
        const size_t nidx = ((size_t)b * TT + (t + 1)) * HH + c;
        const float xwn = out[nidx];     // prefetch next xw (scalar, coalesced)
        const float* hb = &g_h3[par][0][0];

        // ---- stage half0 (k < 512): 4 float4 per thread ----
        {
            float4 v[4];
#pragma unroll
            for (int it = 0; it < 4; it++) {
                const int k = sk + 128 * it;
                v[it] = __ldcg((const float4*)(hb + (size_t)k * BB + b0 + 4 * sg));
            }
#pragma unroll
            for (int it = 0; it < 4; it++) {
                const int k = sk + 128 * it;
                float* dst = Hsm + k;
                dst[(4 * sg + 0) * UPITCH] = v[it].x;
                dst[(4 * sg + 1) * UPITCH] = v[it].y;
                dst[(4 * sg + 2) * UPITCH] = v[it].z;
                dst[(4 * sg + 3) * UPITCH] = v[it].w;
            }
        }
        __syncthreads();

        // ---- issue half1 LDGs (k >= 512), hidden under pass1 ----
        float4 v1[4];
#pragma unroll
        for (int it = 0; it < 4; it++) {
            const int k = 512 + sk + 128 * it;
            v1[it] = __ldcg((const float4*)(hb + (size_t)k * BB + b0 + 4 * sg));
        }

        unsigned long long acc[4][4];
#pragma unroll
        for (int i = 0; i < 4; i++)
#pragma unroll
            for (int q = 0; q < 4; q++) acc[i][q] = 0ull;

        // ---- pass1: strip [kb1, kb1+32) ----
#pragma unroll 8
        for (int kp = 0; kp < 16; kp++) {
            const int k0 = kb1 + 2 * kp;
            unsigned long long a[4], u[4];
#pragma unroll
            for (int i = 0; i < 4; i++)
                a[i] = *(const unsigned long long*)&Hsm[(i * 4 + bg) * UPITCH + k0];
#pragma unroll
            for (int q = 0; q < 4; q++)
                u[q] = *(const unsigned long long*)&Usm[(q * 8 + cg) * UPITCH + k0];
#pragma unroll
            for (int i = 0; i < 4; i++)
#pragma unroll
                for (int q = 0; q < 4; q++)
                    acc[i][q] = ffma2(a[i], u[q], acc[i][q]);
        }

        // ---- store half1 to smem ----
#pragma unroll
        for (int it = 0; it < 4; it++) {
            const int k = 512 + sk + 128 * it;
            float* dst = Hsm + k;
            dst[(4 * sg + 0) * UPITCH] = v1[it].x;
            dst[(4 * sg + 1) * UPITCH] = v1[it].y;
            dst[(4 * sg + 2) * UPITCH] = v1[it].z;
            dst[(4 * sg + 3) * UPITCH] = v1[it].w;
        }
        __syncthreads();

        // ---- pass2: strip [kb2, kb2+32) ----
#pragma unroll 8
        for (int kp = 0; kp < 16; kp++) {
            const int k0 = kb2 + 2 * kp;
            unsigned long long a[4], u[4];
#pragma unroll
            for (int i = 0; i < 4; i++)
                a[i] = *(const unsigned long long*)&Hsm[(i * 4 + bg) * UPITCH + k0];
#pragma unroll
            for (int q = 0; q < 4; q++)
                u[q] = *(const unsigned long long*)&Usm[(q * 8 + cg) * UPITCH + k0];
#pragma unroll
            for (int i = 0; i < 4; i++)
#pragma unroll
                for (int q = 0; q < 4; q++)
                    acc[i][q] = ffma2(a[i], u[q], acc[i][q]);
        }

        // ---- cross-warp reduction (16 partials per output) ----
#pragma unroll
        for (int i = 0; i < 4; i++) {
            const int ob = (i * 4 + bg) * 32;
#pragma unroll
            for (int q = 0; q < 4; q++)
                red[w * 512 + ob + q * 8 + cg] = psum(acc[i][q]);
        }
        __syncthreads();

        float s = bu;
#pragma unroll
        for (int ww = 0; ww < 16; ww++) s += red[ww * 512 + tid];

        const float h0 = tanhf(xwn + s);
        out[nidx] = h0;
        const int par1 = par ^ 1;
        g_h3[par1][c][b] = h0;

        if (t == TT - 2) {
            const size_t o2 = (size_t)BB * TT * HH + (size_t)b * HH + c;
            out[o2] = h0;
            break;
        }

        __threadfence();
        __syncthreads();   // also protects red[]/Hsm reuse
        if (tid == 0) {
            const unsigned int target = (unsigned int)(t + 2);
            if (atomicAdd(&g_cnt4[bslot], 1) == 31) {
                g_cnt4[bslot] = 0;
                __threadfence();
                g_flag4[bslot] = target;
            } else {
                while (g_flag4[bslot] < target) { }
            }
        }
        __syncthreads();
    }
}

extern "C" void kernel_launch(void* const* d_in, const int* in_sizes, int n_in,
                              void* d_out, int out_size) {
    const float* x  = (const float*)d_in[0];
    const float* W  = (const float*)d_in[1];
    const float* bW = (const float*)d_in[2];
    const float* U  = (const float*)d_in[3];
    const float* bU = (const float*)d_in[4];
    float* out = (float*)d_out;

    const int rnn_smem = (48 * UPITCH + 16 * 512) * sizeof(float);
    cudaFuncSetAttribute(rnn_steps_kernel,
                         cudaFuncAttributeMaxDynamicSharedMemorySize, rnn_smem);

    dim3 ggrid(HH / 128, (BB * TT) / 128);  // (8, 256)
    gemm_xw_kernel<<<ggrid, 256>>>(x, W, bW, out);

    rnn_steps_kernel<<<128, 512, rnn_smem>>>(U, bU, out);
}